// round 11
// baseline (speedup 1.0000x reference)
#include <cuda_runtime.h>
#include <cuda_fp16.h>

#define NN 50000
#define EE 800000
#define DD 64
#define LN_EPS 1e-5f
#define GRID2 592          // 148 SMs x 4 resident blocks (launch_bounds enforced)
#define THREADS2 256

// Persistent scratch. Cross-launch invariants restored every call:
//   g_cnt==0 (zeroed by scan), g_deg==0 (zeroed by dinv),
//   g_tstat/g_bar/g_stats/g_work (reset by util block in k_hist)
__device__ __half   g_hh[NN * DD];   // h = x @ W  (fp16)
__device__ float    g_deg[NN];       // weighted in-degree (excl. self loop)
__device__ float    g_dinv[NN];      // (deg+1)^{-1/2}
__device__ int      g_cnt[NN];       // integer in-degree histogram
__device__ int      g_off[NN + 1];   // CSR offsets (+ sentinel = E)
__device__ int      g_eidx[EE];      // within-node slot of each edge
__device__ int2     g_csr[EE];       // {src<<7 (byte off), bits(normWeight)}
__device__ unsigned g_tstat[64];     // scan tile status: (val<<2)|flag
__device__ unsigned g_bar[4];        // phase barriers
__device__ unsigned g_work;          // gemm chunk steal counter
__device__ double   g_stats[2];      // {sum, sumsq}

__device__ __forceinline__ unsigned ldacq(const unsigned* p) {
    unsigned v;
    asm volatile("ld.acquire.gpu.global.b32 %0, [%1];"
                 : "=r"(v) : "l"(p) : "memory");
    return v;
}
__device__ __forceinline__ void strel(unsigned* p, unsigned v) {
    asm volatile("st.release.gpu.global.b32 [%0], %1;"
                 :: "l"(p), "r"(v) : "memory");
}

// grid-wide barrier (all blocks resident by construction)
__device__ __forceinline__ void gbar(unsigned* ctr, unsigned target) {
    __syncthreads();
    if (threadIdx.x == 0) {
        __threadfence();
        atomicAdd(ctr, 1u);
        while (ldacq(ctr) < target) {}
    }
    __syncthreads();
}

// ---------------------------------------------------------------------------
// K1: histogram (+eidx) | last block: reset control state
// ---------------------------------------------------------------------------
__global__ void k_hist(const int* __restrict__ ei, const float* __restrict__ ew,
                       int E, int hist_blks) {
    int bid = blockIdx.x;
    if (bid < hist_blks) {
        int e = bid * 256 + threadIdx.x;
        if (e < E) {
            int c   = ei[E + e];
            float w = ew[e];
            asm volatile("red.global.add.f32 [%0], %1;"
                         :: "l"(&g_deg[c]), "f"(w) : "memory");
            g_eidx[e] = atomicAdd(&g_cnt[c], 1);
        }
    } else {
        if (threadIdx.x < 2)  g_stats[threadIdx.x] = 0.0;
        if (threadIdx.x < 64) g_tstat[threadIdx.x] = 0u;
        if (threadIdx.x < 4)  g_bar[threadIdx.x]   = 0u;
        if (threadIdx.x == 64) g_work = 0u;
    }
}

// ---------------------------------------------------------------------------
// K2 (persistent, GRID2 blocks, 4/SM):
//   p0a: scan tiles (decoupled lookback) | dinv grid-stride
//   p0b: ALL blocks work-steal GEMM chunks (32 rows): h = x @ W -> g_hh fp16
//   p1 : CSR fill (atomic-free), stores src byte-offset
//   p2 : warp-per-node gather + self-loop + bias + stats
//   p3 : graph layernorm + relu
// ---------------------------------------------------------------------------
__global__ void __launch_bounds__(THREADS2, 4)
k_graph(const float* __restrict__ x, const float* __restrict__ W,
        const int* __restrict__ ei, const float* __restrict__ ew,
        const float* __restrict__ b, const float* __restrict__ lnw,
        const float* __restrict__ lnb, float* __restrict__ out,
        int n, int E, int scan_tiles, int gemm_chunks, int nq) {
    int tid = threadIdx.x;
    int bid = blockIdx.x;

    __shared__ float Ws[DD * DD];   // 16 KB
    __shared__ float xs[32 * DD];   // 8 KB
    __shared__ int   wsum[8];
    __shared__ int   s_prefix;
    __shared__ int   s_chunk;

    // ---------------- phase 0a: scan | dinv ----------------
    if (bid < scan_tiles) {
        int i0 = bid * 1024 + tid * 4;
        int v0 = (i0     < n) ? g_cnt[i0]     : 0;
        int v1 = (i0 + 1 < n) ? g_cnt[i0 + 1] : 0;
        int v2 = (i0 + 2 < n) ? g_cnt[i0 + 2] : 0;
        int v3 = (i0 + 3 < n) ? g_cnt[i0 + 3] : 0;
        int T = v0 + v1 + v2 + v3;

        int lane = tid & 31, w = tid >> 5;
        int inc = T;
#pragma unroll
        for (int o = 1; o < 32; o <<= 1) {
            int t = __shfl_up_sync(0xffffffffu, inc, o);
            if (lane >= o) inc += t;
        }
        if (lane == 31) wsum[w] = inc;
        __syncthreads();
        if (w == 0 && lane < 8) {
            int ws = wsum[lane];
#pragma unroll
            for (int o = 1; o < 8; o <<= 1) {
                int t = __shfl_up_sync(0xFFu, ws, o, 8);
                if (lane >= o) ws += t;
            }
            wsum[lane] = ws;
        }
        __syncthreads();
        int excl = inc - T + ((w > 0) ? wsum[w - 1] : 0);
        int agg  = wsum[7];

        if (tid == 0) {
            int prefix = 0;
            if (bid == 0) {
                strel(&g_tstat[0], ((unsigned)agg << 2) | 2u);
            } else {
                strel(&g_tstat[bid], ((unsigned)agg << 2) | 1u);
                for (int j = bid - 1; j >= 0; j--) {
                    unsigned s;
                    do { s = ldacq(&g_tstat[j]); } while ((s & 3u) == 0u);
                    prefix += (int)(s >> 2);
                    if ((s & 3u) == 2u) break;
                }
                strel(&g_tstat[bid], ((unsigned)(prefix + agg) << 2) | 2u);
            }
            s_prefix = prefix;
            if (bid == scan_tiles - 1) g_off[n] = prefix + agg;  // == E
        }
        __syncthreads();
        int pref = s_prefix + excl;
        if (i0     < n) { g_off[i0]     = pref;                g_cnt[i0]     = 0; }
        if (i0 + 1 < n) { g_off[i0 + 1] = pref + v0;           g_cnt[i0 + 1] = 0; }
        if (i0 + 2 < n) { g_off[i0 + 2] = pref + v0 + v1;      g_cnt[i0 + 2] = 0; }
        if (i0 + 3 < n) { g_off[i0 + 3] = pref + v0 + v1 + v2; g_cnt[i0 + 3] = 0; }
    } else {
        for (int i = (bid - scan_tiles) * THREADS2 + tid; i < n;
             i += (GRID2 - scan_tiles) * THREADS2) {
            g_dinv[i] = rsqrtf(g_deg[i] + 1.0f);
            g_deg[i]  = 0.0f;
        }
    }

    // ---------------- phase 0b: work-steal GEMM ----------------
    for (int i = tid; i < DD * DD; i += THREADS2) Ws[i] = W[i];
    __syncthreads();
    while (true) {
        if (tid == 0) s_chunk = (int)atomicAdd(&g_work, 1u);
        __syncthreads();
        int chunk = s_chunk;
        if (chunk >= gemm_chunks) break;
        int base = chunk * 32;
        for (int i = tid; i < 32 * DD; i += THREADS2) {
            int row = base + (i >> 6);
            xs[i] = (row < n) ? x[(size_t)row * DD + (i & 63)] : 0.0f;
        }
        __syncthreads();
        int r0 = tid >> 6;        // 0..3
        int d  = tid & 63;
        float a[8] = {0.f, 0.f, 0.f, 0.f, 0.f, 0.f, 0.f, 0.f};
#pragma unroll
        for (int k4 = 0; k4 < 16; k4++) {
            float wv0 = Ws[(k4 * 4 + 0) * DD + d];
            float wv1 = Ws[(k4 * 4 + 1) * DD + d];
            float wv2 = Ws[(k4 * 4 + 2) * DD + d];
            float wv3 = Ws[(k4 * 4 + 3) * DD + d];
#pragma unroll
            for (int i = 0; i < 8; i++) {
                float4 xv = *reinterpret_cast<const float4*>(
                    &xs[(r0 + i * 4) * DD + k4 * 4]);
                a[i] += xv.x * wv0 + xv.y * wv1 + xv.z * wv2 + xv.w * wv3;
            }
        }
#pragma unroll
        for (int i = 0; i < 8; i++) {
            int row = base + r0 + i * 4;
            if (row < n) g_hh[(size_t)row * DD + d] = __float2half(a[i]);
        }
        __syncthreads();
    }
    gbar(&g_bar[0], GRID2);

    // ---------------- phase 1: CSR fill (src stored as byte offset) --------
    for (int e = bid * THREADS2 + tid; e < E; e += GRID2 * THREADS2) {
        int r = ei[e];
        int c = ei[E + e];
        float wn = g_dinv[r] * ew[e] * g_dinv[c];
        g_csr[g_off[c] + g_eidx[e]] = make_int2(r << 7, __float_as_int(wn));
    }
    gbar(&g_bar[1], GRID2);

    // ---------------- phase 2: warp-per-node gather + stats ----------------
    double ds = 0.0, dq = 0.0;
    {
        const char* hbase = reinterpret_cast<const char*>(g_hh);
        int warp = tid >> 5, lane = tid & 31;
        int lb = lane * 4;                       // byte offset of this lane's half2
        for (int node = bid * 8 + warp; node < n; node += GRID2 * 8) {
            float2 acc = make_float2(0.f, 0.f);
            int p    = g_off[node];
            int pend = g_off[node + 1];
            for (int base = p; base < pend; base += 32) {
                int m = pend - base; if (m > 32) m = 32;
                int2 e = make_int2(0, 0);        // pad: w = +0.0f
                if (base + lane < pend) e = g_csr[base + lane];
                int j = 0;
                for (; j + 1 < m; j += 2) {
                    int   o0 = __shfl_sync(0xffffffffu, e.x, j);
                    float w0 = __int_as_float(__shfl_sync(0xffffffffu, e.y, j));
                    int   o1 = __shfl_sync(0xffffffffu, e.x, j + 1);
                    float w1 = __int_as_float(__shfl_sync(0xffffffffu, e.y, j + 1));
                    __half2 h0 = *reinterpret_cast<const __half2*>(hbase + o0 + lb);
                    __half2 h1 = *reinterpret_cast<const __half2*>(hbase + o1 + lb);
                    float2 f0 = __half22float2(h0);
                    float2 f1 = __half22float2(h1);
                    acc.x += f0.x * w0 + f1.x * w1;
                    acc.y += f0.y * w0 + f1.y * w1;
                }
                if (j < m) {
                    int   o0 = __shfl_sync(0xffffffffu, e.x, j);
                    float w0 = __int_as_float(__shfl_sync(0xffffffffu, e.y, j));
                    __half2 h0 = *reinterpret_cast<const __half2*>(hbase + o0 + lb);
                    float2 f0 = __half22float2(h0);
                    acc.x += f0.x * w0;
                    acc.y += f0.y * w0;
                }
            }
            // self loop + bias
            float di = g_dinv[node];
            float sn = di * di;                  // 1/(deg+1)
            __half2 hs = *reinterpret_cast<const __half2*>(
                hbase + (node << 7) + lb);
            float2 fs = __half22float2(hs);
            float2 bv = *reinterpret_cast<const float2*>(b + lane * 2);
            acc.x += fs.x * sn + bv.x;
            acc.y += fs.y * sn + bv.y;
            *reinterpret_cast<float2*>(out + (size_t)node * DD + lane * 2) = acc;
            ds += (double)(acc.x + acc.y);
            dq += (double)(acc.x * acc.x + acc.y * acc.y);
        }
    }
    {
#pragma unroll
        for (int o = 16; o; o >>= 1) {
            ds += __shfl_down_sync(0xffffffffu, ds, o);
            dq += __shfl_down_sync(0xffffffffu, dq, o);
        }
        __shared__ double sh[16];
        int w = tid >> 5, l = tid & 31;
        if (l == 0) { sh[w] = ds; sh[8 + w] = dq; }
        __syncthreads();
        if (tid == 0) {
            double S = 0.0, Q = 0.0;
#pragma unroll
            for (int i = 0; i < 8; i++) { S += sh[i]; Q += sh[8 + i]; }
            atomicAdd(&g_stats[0], S);
            atomicAdd(&g_stats[1], Q);
        }
    }
    gbar(&g_bar[2], GRID2);

    // ---------------- phase 3: layernorm + relu ----------------
    double S = *(volatile double*)&g_stats[0];
    double Q = *(volatile double*)&g_stats[1];
    double m = S / (double)(n * DD);
    float mean = (float)m;
    float var  = (float)(Q / (double)(n * DD) - m * m);
    var = var > 0.f ? var : 0.f;
    float istd = 1.0f / (sqrtf(var) + LN_EPS);
    for (int t = bid * THREADS2 + tid; t < nq; t += GRID2 * THREADS2) {
        int seg = t & 15;
        float4 v = reinterpret_cast<float4*>(out)[t];
        const float4 wv = *reinterpret_cast<const float4*>(lnw + seg * 4);
        const float4 bv = *reinterpret_cast<const float4*>(lnb + seg * 4);
        v.x = fmaxf((v.x - mean) * istd * wv.x + bv.x, 0.f);
        v.y = fmaxf((v.y - mean) * istd * wv.y + bv.y, 0.f);
        v.z = fmaxf((v.z - mean) * istd * wv.z + bv.z, 0.f);
        v.w = fmaxf((v.w - mean) * istd * wv.w + bv.w, 0.f);
        reinterpret_cast<float4*>(out)[t] = v;
    }
}

// ---------------------------------------------------------------------------
extern "C" void kernel_launch(void* const* d_in, const int* in_sizes, int n_in,
                              void* d_out, int out_size) {
    const float* x   = (const float*)d_in[0];
    const float* ew  = (const float*)d_in[1];
    const float* W   = (const float*)d_in[2];
    const float* b   = (const float*)d_in[3];
    const float* lnw = (const float*)d_in[4];
    const float* lnb = (const float*)d_in[5];
    const int*   ei  = (const int*)d_in[6];

    int N = in_sizes[0] / DD;
    int E = in_sizes[1];
    float* out = (float*)d_out;

    int hist_blks   = (E + 255) / 256;
    int scan_tiles  = (N + 1023) / 1024;   // 49 (< 64 tstat slots, < GRID2)
    int gemm_chunks = (N + 31) / 32;       // 1563
    int nq          = N * (DD / 4);

    k_hist <<<hist_blks + 1, 256>>>(ei, ew, E, hist_blks);
    k_graph<<<GRID2, THREADS2>>>(x, W, ei, ew, b, lnw, lnb, out,
                                 N, E, scan_tiles, gemm_chunks, nq);
}

// round 12
// speedup vs baseline: 1.3928x; 1.3928x over previous
#include <cuda_runtime.h>
#include <cuda_fp16.h>

#define NN 50000
#define EE 800000
#define DD 64
#define LN_EPS 1e-5f
#define GRID2 592          // 148 SMs x 4 resident blocks (launch_bounds enforced)
#define THREADS2 256
#define SPLIT 356          // blocks [0,SPLIT) = graph path, [SPLIT,GRID2) = gemm

// Persistent scratch. Control state (g_bar/g_work/g_stats/g_tstat) is reset at
// the END of k_graph behind an ack barrier; g_cnt zeroed by scan, g_deg by
// dinv => graph-replay deterministic. All globals statically zero for call 0.
__device__ __half   g_hh[NN * DD];   // h = x @ W  (fp16)
__device__ float    g_deg[NN];       // weighted in-degree (excl. self loop)
__device__ float    g_dinv[NN];      // (deg+1)^{-1/2}
__device__ int      g_cnt[NN];       // integer in-degree histogram
__device__ int      g_off[NN + 1];   // CSR offsets (+ sentinel = E)
__device__ int      g_eidx[EE];      // within-node slot of each edge
__device__ int2     g_csr[EE];       // {src, bits(normWeight)}
__device__ unsigned g_tstat[64];     // scan tile status: (val<<2)|flag
__device__ unsigned g_bar[8];        // [0]=histA [1]=scanA [2]=all0 [3]=all1 [7]=ack
__device__ unsigned g_work;          // gemm chunk steal counter
__device__ double   g_stats[2];      // {sum, sumsq}

__device__ __forceinline__ unsigned ldacq(const unsigned* p) {
    unsigned v;
    asm volatile("ld.acquire.gpu.global.b32 %0, [%1];"
                 : "=r"(v) : "l"(p) : "memory");
    return v;
}
__device__ __forceinline__ void strel(unsigned* p, unsigned v) {
    asm volatile("st.release.gpu.global.b32 [%0], %1;"
                 :: "l"(p), "r"(v) : "memory");
}

// barrier over a set of resident blocks (all GRID2 blocks are co-resident)
__device__ __forceinline__ void gbar(unsigned* ctr, unsigned target) {
    __syncthreads();
    if (threadIdx.x == 0) {
        __threadfence();
        atomicAdd(ctr, 1u);
        while (ldacq(ctr) < target) {}
    }
    __syncthreads();
}

// fma 8 halfs (packed in uint4) * w into 8 fp32 accumulators
__device__ __forceinline__ void fma8(float* acc, uint4 r, float w) {
    const __half2* h = reinterpret_cast<const __half2*>(&r);
#pragma unroll
    for (int i = 0; i < 4; i++) {
        float2 f = __half22float2(h[i]);
        acc[2 * i]     += f.x * w;
        acc[2 * i + 1] += f.y * w;
    }
}

// ---------------------------------------------------------------------------
// Single persistent kernel, static two-group split.
//  A (bid<SPLIT):  hist -> barA -> scan|dinv -> barA2 -> fill
//  B (bid>=SPLIT): gemm work-steal (x @ W -> g_hh fp16)
//  all:            bar_all -> gather+stats -> bar_all2 -> norm -> ack/reset
// ---------------------------------------------------------------------------
__global__ void __launch_bounds__(THREADS2, 4)
k_graph(const float* __restrict__ x, const float* __restrict__ W,
        const int* __restrict__ ei, const float* __restrict__ ew,
        const float* __restrict__ b, const float* __restrict__ lnw,
        const float* __restrict__ lnb, float* __restrict__ out,
        int n, int E, int scan_tiles, int gemm_chunks, int nchunks, int nq) {
    int tid = threadIdx.x;
    int bid = blockIdx.x;

    __shared__ float Ws[DD * DD];   // 16 KB (B path)
    __shared__ float xs[32 * DD];   // 8 KB  (B path)
    __shared__ int   wsum[8];
    __shared__ int   s_prefix;
    __shared__ int   s_chunk;

    if (bid < SPLIT) {
        // ================= group A =================
        // ---- A0: histogram (+eidx) ----
        for (int e = bid * THREADS2 + tid; e < E; e += SPLIT * THREADS2) {
            int c   = ei[E + e];
            float w = ew[e];
            asm volatile("red.global.add.f32 [%0], %1;"
                         :: "l"(&g_deg[c]), "f"(w) : "memory");
            g_eidx[e] = atomicAdd(&g_cnt[c], 1);
        }
        gbar(&g_bar[0], SPLIT);

        // ---- A1: scan (decoupled lookback) | dinv ----
        if (bid < scan_tiles) {
            int i0 = bid * 1024 + tid * 4;
            int v0 = (i0     < n) ? g_cnt[i0]     : 0;
            int v1 = (i0 + 1 < n) ? g_cnt[i0 + 1] : 0;
            int v2 = (i0 + 2 < n) ? g_cnt[i0 + 2] : 0;
            int v3 = (i0 + 3 < n) ? g_cnt[i0 + 3] : 0;
            int T = v0 + v1 + v2 + v3;

            int lane = tid & 31, w = tid >> 5;
            int inc = T;
#pragma unroll
            for (int o = 1; o < 32; o <<= 1) {
                int t = __shfl_up_sync(0xffffffffu, inc, o);
                if (lane >= o) inc += t;
            }
            if (lane == 31) wsum[w] = inc;
            __syncthreads();
            if (w == 0 && lane < 8) {
                int ws = wsum[lane];
#pragma unroll
                for (int o = 1; o < 8; o <<= 1) {
                    int t = __shfl_up_sync(0xFFu, ws, o, 8);
                    if (lane >= o) ws += t;
                }
                wsum[lane] = ws;
            }
            __syncthreads();
            int excl = inc - T + ((w > 0) ? wsum[w - 1] : 0);
            int agg  = wsum[7];

            if (tid == 0) {
                int prefix = 0;
                if (bid == 0) {
                    strel(&g_tstat[0], ((unsigned)agg << 2) | 2u);
                } else {
                    strel(&g_tstat[bid], ((unsigned)agg << 2) | 1u);
                    for (int j = bid - 1; j >= 0; j--) {
                        unsigned s;
                        do { s = ldacq(&g_tstat[j]); } while ((s & 3u) == 0u);
                        prefix += (int)(s >> 2);
                        if ((s & 3u) == 2u) break;
                    }
                    strel(&g_tstat[bid], ((unsigned)(prefix + agg) << 2) | 2u);
                }
                s_prefix = prefix;
                if (bid == scan_tiles - 1) g_off[n] = prefix + agg;  // == E
            }
            __syncthreads();
            int pref = s_prefix + excl;
            if (i0     < n) { g_off[i0]     = pref;                g_cnt[i0]     = 0; }
            if (i0 + 1 < n) { g_off[i0 + 1] = pref + v0;           g_cnt[i0 + 1] = 0; }
            if (i0 + 2 < n) { g_off[i0 + 2] = pref + v0 + v1;      g_cnt[i0 + 2] = 0; }
            if (i0 + 3 < n) { g_off[i0 + 3] = pref + v0 + v1 + v2; g_cnt[i0 + 3] = 0; }
        } else {
            for (int i = (bid - scan_tiles) * THREADS2 + tid; i < n;
                 i += (SPLIT - scan_tiles) * THREADS2) {
                g_dinv[i] = rsqrtf(g_deg[i] + 1.0f);
                g_deg[i]  = 0.0f;
            }
        }
        gbar(&g_bar[1], SPLIT);

        // ---- A2: CSR fill (atomic-free) ----
        for (int e = bid * THREADS2 + tid; e < E; e += SPLIT * THREADS2) {
            int r = ei[e];
            int c = ei[E + e];
            float wn = g_dinv[r] * ew[e] * g_dinv[c];
            g_csr[g_off[c] + g_eidx[e]] = make_int2(r, __float_as_int(wn));
        }
    } else {
        // ================= group B: work-steal GEMM =================
        for (int i = tid; i < DD * DD; i += THREADS2) Ws[i] = W[i];
        __syncthreads();
        while (true) {
            if (tid == 0) s_chunk = (int)atomicAdd(&g_work, 1u);
            __syncthreads();
            int chunk = s_chunk;
            if (chunk >= gemm_chunks) break;
            int base = chunk * 32;
            for (int i = tid; i < 32 * DD; i += THREADS2) {
                int row = base + (i >> 6);
                xs[i] = (row < n) ? x[(size_t)row * DD + (i & 63)] : 0.0f;
            }
            __syncthreads();
            int r0 = tid >> 6;        // 0..3
            int d  = tid & 63;
            float a[8] = {0.f, 0.f, 0.f, 0.f, 0.f, 0.f, 0.f, 0.f};
#pragma unroll
            for (int k4 = 0; k4 < 16; k4++) {
                float wv0 = Ws[(k4 * 4 + 0) * DD + d];
                float wv1 = Ws[(k4 * 4 + 1) * DD + d];
                float wv2 = Ws[(k4 * 4 + 2) * DD + d];
                float wv3 = Ws[(k4 * 4 + 3) * DD + d];
#pragma unroll
                for (int i = 0; i < 8; i++) {
                    float4 xv = *reinterpret_cast<const float4*>(
                        &xs[(r0 + i * 4) * DD + k4 * 4]);
                    a[i] += xv.x * wv0 + xv.y * wv1 + xv.z * wv2 + xv.w * wv3;
                }
            }
#pragma unroll
            for (int i = 0; i < 8; i++) {
                int row = base + r0 + i * 4;
                if (row < n) g_hh[(size_t)row * DD + d] = __float2half(a[i]);
            }
            __syncthreads();
        }
    }
    gbar(&g_bar[2], GRID2);

    // ---------------- gather + stats (all blocks) ----------------
    double ds = 0.0, dq = 0.0;
    const uint4* hrow = reinterpret_cast<const uint4*>(g_hh);
    for (int chunk = bid; chunk < nchunks; chunk += GRID2) {
        int node = chunk * 32 + (tid >> 3);
        int sub  = tid & 7;               // feature octet
        if (node < n) {
            float acc[8] = {0.f, 0.f, 0.f, 0.f, 0.f, 0.f, 0.f, 0.f};
            int p    = g_off[node];
            int pend = g_off[node + 1];
            int i = p;
            for (; i + 3 < pend; i += 4) {
                int2 e0 = g_csr[i];
                int2 e1 = g_csr[i + 1];
                int2 e2 = g_csr[i + 2];
                int2 e3 = g_csr[i + 3];
                uint4 r0 = hrow[(size_t)e0.x * 8 + sub];
                uint4 r1 = hrow[(size_t)e1.x * 8 + sub];
                uint4 r2 = hrow[(size_t)e2.x * 8 + sub];
                uint4 r3 = hrow[(size_t)e3.x * 8 + sub];
                fma8(acc, r0, __int_as_float(e0.y));
                fma8(acc, r1, __int_as_float(e1.y));
                fma8(acc, r2, __int_as_float(e2.y));
                fma8(acc, r3, __int_as_float(e3.y));
            }
            for (; i < pend; i++) {
                int2 e0 = g_csr[i];
                uint4 r0 = hrow[(size_t)e0.x * 8 + sub];
                fma8(acc, r0, __int_as_float(e0.y));
            }
            float di = g_dinv[node];
            float sn = di * di;           // self-loop norm = 1/(deg+1)
            uint4 rs = hrow[(size_t)node * 8 + sub];
            fma8(acc, rs, sn);
            const float4 bv0 = *reinterpret_cast<const float4*>(b + sub * 8);
            const float4 bv1 = *reinterpret_cast<const float4*>(b + sub * 8 + 4);
            acc[0] += bv0.x; acc[1] += bv0.y; acc[2] += bv0.z; acc[3] += bv0.w;
            acc[4] += bv1.x; acc[5] += bv1.y; acc[6] += bv1.z; acc[7] += bv1.w;
            float4* orow = reinterpret_cast<float4*>(out + (size_t)node * DD + sub * 8);
            orow[0] = make_float4(acc[0], acc[1], acc[2], acc[3]);
            orow[1] = make_float4(acc[4], acc[5], acc[6], acc[7]);
            float s = 0.f, sq = 0.f;
#pragma unroll
            for (int k = 0; k < 8; k++) { s += acc[k]; sq += acc[k] * acc[k]; }
            ds += (double)s; dq += (double)sq;
        }
    }
    {
#pragma unroll
        for (int o = 16; o; o >>= 1) {
            ds += __shfl_down_sync(0xffffffffu, ds, o);
            dq += __shfl_down_sync(0xffffffffu, dq, o);
        }
        __shared__ double sh[16];
        int w = tid >> 5, l = tid & 31;
        if (l == 0) { sh[w] = ds; sh[8 + w] = dq; }
        __syncthreads();
        if (tid == 0) {
            double S = 0.0, Q = 0.0;
#pragma unroll
            for (int i = 0; i < 8; i++) { S += sh[i]; Q += sh[8 + i]; }
            atomicAdd(&g_stats[0], S);
            atomicAdd(&g_stats[1], Q);
        }
    }
    gbar(&g_bar[3], GRID2);

    // ---------------- layernorm + relu ----------------
    double S = *(volatile double*)&g_stats[0];
    double Q = *(volatile double*)&g_stats[1];
    double m = S / (double)(n * DD);
    float mean = (float)m;
    float var  = (float)(Q / (double)(n * DD) - m * m);
    var = var > 0.f ? var : 0.f;
    float istd = 1.0f / (sqrtf(var) + LN_EPS);
    for (int t = bid * THREADS2 + tid; t < nq; t += GRID2 * THREADS2) {
        int seg = t & 15;
        float4 v = reinterpret_cast<float4*>(out)[t];
        const float4 wv = *reinterpret_cast<const float4*>(lnw + seg * 4);
        const float4 bv = *reinterpret_cast<const float4*>(lnb + seg * 4);
        v.x = fmaxf((v.x - mean) * istd * wv.x + bv.x, 0.f);
        v.y = fmaxf((v.y - mean) * istd * wv.y + bv.y, 0.f);
        v.z = fmaxf((v.z - mean) * istd * wv.z + bv.z, 0.f);
        v.w = fmaxf((v.w - mean) * istd * wv.w + bv.w, 0.f);
        reinterpret_cast<float4*>(out)[t] = v;
    }

    // ---------------- ack + control-state reset (graph-replay safe) --------
    __syncthreads();
    if (tid == 0) {
        __threadfence();
        atomicAdd(&g_bar[7], 1u);           // past all barriers
        if (bid == 0) {
            while (ldacq(&g_bar[7]) < GRID2) {}
#pragma unroll
            for (int i = 0; i < 8; i++) g_bar[i] = 0u;
            g_work = 0u;
            g_stats[0] = 0.0; g_stats[1] = 0.0;
            for (int i = 0; i < 64; i++) g_tstat[i] = 0u;
        }
    }
}

// ---------------------------------------------------------------------------
extern "C" void kernel_launch(void* const* d_in, const int* in_sizes, int n_in,
                              void* d_out, int out_size) {
    const float* x   = (const float*)d_in[0];
    const float* ew  = (const float*)d_in[1];
    const float* W   = (const float*)d_in[2];
    const float* b   = (const float*)d_in[3];
    const float* lnw = (const float*)d_in[4];
    const float* lnb = (const float*)d_in[5];
    const int*   ei  = (const int*)d_in[6];

    int N = in_sizes[0] / DD;
    int E = in_sizes[1];
    float* out = (float*)d_out;

    int scan_tiles  = (N + 1023) / 1024;   // 49 (< 64 tstat slots, < SPLIT)
    int gemm_chunks = (N + 31) / 32;       // 1563
    int nchunks     = (N + 31) / 32;
    int nq          = N * (DD / 4);

    k_graph<<<GRID2, THREADS2>>>(x, W, ei, ew, b, lnw, lnb, out,
                                 N, E, scan_tiles, gemm_chunks, nchunks, nq);
}